// round 1
// baseline (speedup 1.0000x reference)
#include <cuda_runtime.h>
#include <cuda_bf16.h>

// ---------------- fixed problem constants (SUBDIVISIONS=7) ----------------
#define BATCH   16
#define XDIM    256
#define YDIM    640
#define NGRID   (YDIM * XDIM)      // 163840
#define NVERTS  (NGRID + 2)        // 163842
#define NFACES  327680
#define BH      128                // Y / 5

// ---------------- device scratch (no allocation allowed) ------------------
__device__ float4 g_v[(size_t)NVERTS * BATCH];   // [vertex][batch], ~42MB
__device__ int2   g_inc[6 * (size_t)NVERTS];     // slot-major incidence, ~7.9MB
__device__ int    g_cnt[NVERTS];
__device__ double g_acc[2];                      // [0]=sum of sq terms, [1]=sum of (1-cos)

// ---------------- kernels -------------------------------------------------
__global__ void k_zero() {
    int i = blockIdx.x * blockDim.x + threadIdx.x;
    if (i < NVERTS) g_cnt[i] = 0;
    if (i < 2) g_acc[i] = 0.0;
}

// Build v[vertex][batch] (float4, w=0). grid: (ceil(NVERTS/256), 8), 2 batches/thread.
__global__ void k_build_v(const float* __restrict__ in) {
    int i  = blockIdx.x * blockDim.x + threadIdx.x;
    int b0 = blockIdx.y * 2;
    if (i >= NVERTS) return;
    if (i < NGRID) {
        #pragma unroll
        for (int bb = 0; bb < 2; bb++) {
            int b = b0 + bb;
            const float* p = in + (size_t)b * 3 * NGRID + i;
            float x = p[0];
            float y = p[NGRID];
            float z = p[2 * NGRID];
            g_v[(size_t)i * BATCH + b] = make_float4(x, y, z, 0.f);
        }
    } else {
        // pole vertices: i==NGRID -> top mean, i==NGRID+1 -> bot mean
        bool top = (i == NGRID);
        #pragma unroll
        for (int bb = 0; bb < 2; bb++) {
            int b = b0 + bb;
            float ax = 0.f, ay = 0.f, az = 0.f;
            #pragma unroll
            for (int k = 0; k < 5; k++) {
                int n = top ? (k * BH) * XDIM
                            : (k * BH + BH - 1) * XDIM + (XDIM - 1);
                const float* p = in + (size_t)b * 3 * NGRID + n;
                ax += p[0];
                ay += p[NGRID];
                az += p[2 * NGRID];
            }
            g_v[(size_t)i * BATCH + b] = make_float4(ax * 0.2f, ay * 0.2f, az * 0.2f, 0.f);
        }
    }
}

// Build slot-major incidence. For corner vertex v of face (a,b,c), store the
// other two corners in cyclic order so cross(vj - vi, vk - vi) == face normal.
__global__ void k_build_inc(const int* __restrict__ faces) {
    int f = blockIdx.x * blockDim.x + threadIdx.x;
    if (f >= NFACES) return;
    int a = faces[3 * f + 0];
    int b = faces[3 * f + 1];
    int c = faces[3 * f + 2];
    int p;
    p = atomicAdd(&g_cnt[a], 1); g_inc[(size_t)p * NVERTS + a] = make_int2(b, c);
    p = atomicAdd(&g_cnt[b], 1); g_inc[(size_t)p * NVERTS + b] = make_int2(c, a);
    p = atomicAdd(&g_cnt[c], 1); g_inc[(size_t)p * NVERTS + c] = make_int2(a, b);
}

__device__ __forceinline__ void per_batch_loss(
    float vix, float viy, float viz,
    float nx, float ny, float nz,
    float sx, float sy, float sz,
    float invd,
    const float* __restrict__ tb,   // target + b*9*NVERTS + i
    float& sq, float& nor)
{
    // target channels (stride NVERTS, coalesced across warp)
    float tvx = tb[0];
    float tvy = tb[(size_t)1 * NVERTS];
    float tvz = tb[(size_t)2 * NVERTS];
    float tnx = tb[(size_t)3 * NVERTS];
    float tny = tb[(size_t)4 * NVERTS];
    float tnz = tb[(size_t)5 * NVERTS];
    float tlx = tb[(size_t)6 * NVERTS];
    float tly = tb[(size_t)7 * NVERTS];
    float tlz = tb[(size_t)8 * NVERTS];

    // positional MSE term
    float dx = vix - tvx, dy = viy - tvy, dz = viz - tvz;
    sq += dx * dx + dy * dy + dz * dz;

    // laplacian: lap = v - 0.5*S/deg  (each neighbor counted twice in S)
    float lx = vix - 0.5f * sx * invd - tlx;
    float ly = viy - 0.5f * sy * invd - tly;
    float lz = viz - 0.5f * sz * invd - tlz;
    sq += lx * lx + ly * ly + lz * lz;

    // normal cosine term
    float nv = sqrtf(nx * nx + ny * ny + nz * nz);
    nv = fmaxf(nv, 1e-12f);
    float tnorm = sqrtf(tnx * tnx + tny * tny + tnz * tnz);
    float dot = nx * tnx + ny * tny + nz * tnz;
    float c = dot / fmaxf(nv * tnorm, 1e-8f * nv);  // == (vn/|vn|)·tn / max(1*|tn|,1e-8)
    nor += 1.0f - c;
}

// Main fused kernel: grid (ceil(NVERTS/256), 8), each thread = (vertex, batch pair)
__global__ __launch_bounds__(256) void k_main(const float* __restrict__ tgt,
                                              const float* __restrict__ degree)
{
    int i  = blockIdx.x * blockDim.x + threadIdx.x;
    int b0 = blockIdx.y * 2;
    float sq = 0.f, nor = 0.f;

    if (i < NVERTS) {
        float degf = degree[i];
        int   deg  = (int)degf;
        float invd = 1.0f / degf;

        float4 vi0 = __ldg(&g_v[(size_t)i * BATCH + b0]);
        float4 vi1 = __ldg(&g_v[(size_t)i * BATCH + b0 + 1]);

        float nx0 = 0.f, ny0 = 0.f, nz0 = 0.f, sx0 = 0.f, sy0 = 0.f, sz0 = 0.f;
        float nx1 = 0.f, ny1 = 0.f, nz1 = 0.f, sx1 = 0.f, sy1 = 0.f, sz1 = 0.f;

        #pragma unroll
        for (int t = 0; t < 6; t++) {
            if (t < deg) {
                int2 jk = __ldg(&g_inc[(size_t)t * NVERTS + i]);
                size_t ja = (size_t)jk.x * BATCH + b0;
                size_t ka = (size_t)jk.y * BATCH + b0;
                float4 a0 = __ldg(&g_v[ja]);
                float4 a1 = __ldg(&g_v[ja + 1]);
                float4 c0 = __ldg(&g_v[ka]);
                float4 c1 = __ldg(&g_v[ka + 1]);

                // batch b0: fn = cross(a - vi, c - vi)
                {
                    float e1x = a0.x - vi0.x, e1y = a0.y - vi0.y, e1z = a0.z - vi0.z;
                    float e2x = c0.x - vi0.x, e2y = c0.y - vi0.y, e2z = c0.z - vi0.z;
                    nx0 += e1y * e2z - e1z * e2y;
                    ny0 += e1z * e2x - e1x * e2z;
                    nz0 += e1x * e2y - e1y * e2x;
                    sx0 += a0.x + c0.x;
                    sy0 += a0.y + c0.y;
                    sz0 += a0.z + c0.z;
                }
                // batch b0+1
                {
                    float e1x = a1.x - vi1.x, e1y = a1.y - vi1.y, e1z = a1.z - vi1.z;
                    float e2x = c1.x - vi1.x, e2y = c1.y - vi1.y, e2z = c1.z - vi1.z;
                    nx1 += e1y * e2z - e1z * e2y;
                    ny1 += e1z * e2x - e1x * e2z;
                    nz1 += e1x * e2y - e1y * e2x;
                    sx1 += a1.x + c1.x;
                    sy1 += a1.y + c1.y;
                    sz1 += a1.z + c1.z;
                }
            }
        }

        const float* tb0 = tgt + (size_t)b0 * 9 * NVERTS + i;
        const float* tb1 = tgt + (size_t)(b0 + 1) * 9 * NVERTS + i;
        per_batch_loss(vi0.x, vi0.y, vi0.z, nx0, ny0, nz0, sx0, sy0, sz0, invd, tb0, sq, nor);
        per_batch_loss(vi1.x, vi1.y, vi1.z, nx1, ny1, nz1, sx1, sy1, sz1, invd, tb1, sq, nor);
    }

    // block reduction
    #pragma unroll
    for (int o = 16; o > 0; o >>= 1) {
        sq  += __shfl_down_sync(0xFFFFFFFFu, sq,  o);
        nor += __shfl_down_sync(0xFFFFFFFFu, nor, o);
    }
    __shared__ float s_sq[8], s_nor[8];
    int lane = threadIdx.x & 31, wid = threadIdx.x >> 5;
    if (lane == 0) { s_sq[wid] = sq; s_nor[wid] = nor; }
    __syncthreads();
    if (threadIdx.x == 0) {
        float a = 0.f, b = 0.f;
        #pragma unroll
        for (int w = 0; w < 8; w++) { a += s_sq[w]; b += s_nor[w]; }
        atomicAdd(&g_acc[0], (double)a);
        atomicAdd(&g_acc[1], (double)b);
    }
}

__global__ void k_final(float* __restrict__ out) {
    double l_sq  = g_acc[0] / ((double)BATCH * (double)NVERTS * 3.0);
    double l_nor = g_acc[1] / ((double)BATCH * (double)NVERTS);
    out[0] = (float)(l_sq + l_nor);
}

// ---------------- launch --------------------------------------------------
extern "C" void kernel_launch(void* const* d_in, const int* in_sizes, int n_in,
                              void* d_out, int out_size)
{
    const float* inputs = (const float*)d_in[0];
    const float* target = (const float*)d_in[1];
    const int*   faces  = (const int*)d_in[2];
    // d_in[3]=edge_src, d_in[4]=edge_dst : not needed (derived from incidence)
    const float* degree = (const float*)d_in[5];
    float* out = (float*)d_out;

    int nbv = (NVERTS + 255) / 256;
    int nbf = (NFACES + 255) / 256;

    k_zero<<<nbv, 256>>>();
    k_build_v<<<dim3(nbv, BATCH / 2), 256>>>(inputs);
    k_build_inc<<<nbf, 256>>>(faces);
    k_main<<<dim3(nbv, BATCH / 2), 256>>>(target, degree);
    k_final<<<1, 1>>>(out);
}

// round 3
// speedup vs baseline: 1.3270x; 1.3270x over previous
#include <cuda_runtime.h>
#include <cuda_bf16.h>

// ---------------- fixed problem constants (SUBDIVISIONS=7) ----------------
#define BATCH   16
#define XDIM    256
#define YDIM    640
#define NGRID   (YDIM * XDIM)      // 163840
#define NVERTS  (NGRID + 2)        // 163842
#define NFACES  327680
#define BH      128                // Y / 5

// ---------------- device scratch (no allocation allowed) ------------------
__device__ float4 g_v[(size_t)NVERTS * BATCH];   // [vertex][batch], ~42MB
__device__ int2   g_inc[6 * (size_t)NVERTS];     // slot-major incidence pairs
__device__ int    g_ring[6 * (size_t)NVERTS];    // slot-major ordered neighbor ring
__device__ int    g_cnt[NVERTS];
__device__ double g_acc[2];                      // [0]=sum sq terms, [1]=sum (1-cos)

// ---------------- kernels -------------------------------------------------
__global__ void k_zero() {
    int i = blockIdx.x * blockDim.x + threadIdx.x;
    if (i < NVERTS) g_cnt[i] = 0;
    if (i < 2) g_acc[i] = 0.0;
}

// Build v[vertex][batch] (float4, w=0). grid: (ceil(NVERTS/256), 8), 2 batches/thread.
__global__ void k_build_v(const float* __restrict__ in) {
    int i  = blockIdx.x * blockDim.x + threadIdx.x;
    int b0 = blockIdx.y * 2;
    if (i >= NVERTS) return;
    if (i < NGRID) {
        #pragma unroll
        for (int bb = 0; bb < 2; bb++) {
            int b = b0 + bb;
            const float* p = in + (size_t)b * 3 * NGRID + i;
            float x = p[0];
            float y = p[NGRID];
            float z = p[2 * NGRID];
            g_v[(size_t)i * BATCH + b] = make_float4(x, y, z, 0.f);
        }
    } else {
        bool top = (i == NGRID);
        #pragma unroll
        for (int bb = 0; bb < 2; bb++) {
            int b = b0 + bb;
            float ax = 0.f, ay = 0.f, az = 0.f;
            #pragma unroll
            for (int k = 0; k < 5; k++) {
                int n = top ? (k * BH) * XDIM
                            : (k * BH + BH - 1) * XDIM + (XDIM - 1);
                const float* p = in + (size_t)b * 3 * NGRID + n;
                ax += p[0];
                ay += p[NGRID];
                az += p[2 * NGRID];
            }
            g_v[(size_t)i * BATCH + b] = make_float4(ax * 0.2f, ay * 0.2f, az * 0.2f, 0.f);
        }
    }
}

// Oriented incidence: for corner v of face (a,b,c), store the other two
// corners cyclically so cross(vj - vi, vk - vi) == face normal.
__global__ void k_build_inc(const int* __restrict__ faces) {
    int f = blockIdx.x * blockDim.x + threadIdx.x;
    if (f >= NFACES) return;
    int a = faces[3 * f + 0];
    int b = faces[3 * f + 1];
    int c = faces[3 * f + 2];
    int p;
    p = atomicAdd(&g_cnt[a], 1); g_inc[(size_t)p * NVERTS + a] = make_int2(b, c);
    p = atomicAdd(&g_cnt[b], 1); g_inc[(size_t)p * NVERTS + b] = make_int2(c, a);
    p = atomicAdd(&g_cnt[c], 1); g_inc[(size_t)p * NVERTS + c] = make_int2(a, b);
}

// Chain the (j,k) pairs into an ordered closed ring: face t = (ring[t], ring[t+1]).
// Each neighbor appears exactly once as a pair's .x (closed oriented fan).
__global__ void k_build_ring(const float* __restrict__ degree) {
    int i = blockIdx.x * blockDim.x + threadIdx.x;
    if (i >= NVERTS) return;
    int deg = (int)degree[i];
    int2 p[6];
    #pragma unroll
    for (int t = 0; t < 6; t++)
        p[t] = (t < deg) ? g_inc[(size_t)t * NVERTS + i] : make_int2(-1, -2);

    int cur = p[0].x;
    #pragma unroll
    for (int t = 0; t < 6; t++) {
        if (t < deg) {
            g_ring[(size_t)t * NVERTS + i] = cur;
            // advance: find pair whose .x == cur; its .y is the ring successor
            int nxt = cur;
            #pragma unroll
            for (int s = 0; s < 6; s++)
                if (p[s].x == cur) nxt = p[s].y;
            cur = nxt;
        }
    }
}

__device__ __forceinline__ void per_batch_loss(
    float vix, float viy, float viz,
    float nx, float ny, float nz,
    float sx, float sy, float sz,
    float invd,
    const float* __restrict__ tb,   // target + b*9*NVERTS + i
    float& sq, float& nor)
{
    float tvx = tb[0];
    float tvy = tb[(size_t)1 * NVERTS];
    float tvz = tb[(size_t)2 * NVERTS];
    float tnx = tb[(size_t)3 * NVERTS];
    float tny = tb[(size_t)4 * NVERTS];
    float tnz = tb[(size_t)5 * NVERTS];
    float tlx = tb[(size_t)6 * NVERTS];
    float tly = tb[(size_t)7 * NVERTS];
    float tlz = tb[(size_t)8 * NVERTS];

    // positional MSE term
    float dx = vix - tvx, dy = viy - tvy, dz = viz - tvz;
    sq += dx * dx + dy * dy + dz * dz;

    // laplacian: lap = v - S/deg  (S = exact neighbor sum from the ring)
    float lx = vix - sx * invd - tlx;
    float ly = viy - sy * invd - tly;
    float lz = viz - sz * invd - tlz;
    sq += lx * lx + ly * ly + lz * lz;

    // normal cosine term
    float nv = sqrtf(nx * nx + ny * ny + nz * nz);
    nv = fmaxf(nv, 1e-12f);
    float tnorm = sqrtf(tnx * tnx + tny * tny + tnz * tnz);
    float dot = nx * tnx + ny * tny + nz * tnz;
    float c = dot / fmaxf(nv * tnorm, 1e-8f * nv);
    nor += 1.0f - c;
}

// Main fused kernel: grid (ceil(NVERTS/256), 8), each thread = (vertex, batch pair)
__global__ __launch_bounds__(256) void k_main(const float* __restrict__ tgt,
                                              const float* __restrict__ degree)
{
    int i  = blockIdx.x * blockDim.x + threadIdx.x;
    int b0 = blockIdx.y * 2;
    float sq = 0.f, nor = 0.f;

    if (i < NVERTS) {
        float degf = degree[i];
        int   deg  = (int)degf;
        float invd = 1.0f / degf;

        float4 vi0 = __ldg(&g_v[(size_t)i * BATCH + b0]);
        float4 vi1 = __ldg(&g_v[(size_t)i * BATCH + b0 + 1]);

        float nx0 = 0.f, ny0 = 0.f, nz0 = 0.f, sx0 = 0.f, sy0 = 0.f, sz0 = 0.f;
        float nx1 = 0.f, ny1 = 0.f, nz1 = 0.f, sx1 = 0.f, sy1 = 0.f, sz1 = 0.f;

        // first ring vertex
        int r0 = __ldg(&g_ring[i]);
        float4 fst0 = __ldg(&g_v[(size_t)r0 * BATCH + b0]);
        float4 fst1 = __ldg(&g_v[(size_t)r0 * BATCH + b0 + 1]);
        sx0 += fst0.x; sy0 += fst0.y; sz0 += fst0.z;
        sx1 += fst1.x; sy1 += fst1.y; sz1 += fst1.z;
        float4 pv0 = fst0, pv1 = fst1;

        #pragma unroll
        for (int t = 1; t < 6; t++) {
            if (t < deg) {
                int r = __ldg(&g_ring[(size_t)t * NVERTS + i]);
                float4 c0 = __ldg(&g_v[(size_t)r * BATCH + b0]);
                float4 c1 = __ldg(&g_v[(size_t)r * BATCH + b0 + 1]);
                sx0 += c0.x; sy0 += c0.y; sz0 += c0.z;
                sx1 += c1.x; sy1 += c1.y; sz1 += c1.z;
                // fn = cross(prev - vi, cur - vi)
                {
                    float e1x = pv0.x - vi0.x, e1y = pv0.y - vi0.y, e1z = pv0.z - vi0.z;
                    float e2x = c0.x - vi0.x,  e2y = c0.y - vi0.y,  e2z = c0.z - vi0.z;
                    nx0 += e1y * e2z - e1z * e2y;
                    ny0 += e1z * e2x - e1x * e2z;
                    nz0 += e1x * e2y - e1y * e2x;
                }
                {
                    float e1x = pv1.x - vi1.x, e1y = pv1.y - vi1.y, e1z = pv1.z - vi1.z;
                    float e2x = c1.x - vi1.x,  e2y = c1.y - vi1.y,  e2z = c1.z - vi1.z;
                    nx1 += e1y * e2z - e1z * e2y;
                    ny1 += e1z * e2x - e1x * e2z;
                    nz1 += e1x * e2y - e1y * e2x;
                }
                pv0 = c0; pv1 = c1;
            }
        }
        // closing face: (last, first)
        {
            float e1x = pv0.x - vi0.x, e1y = pv0.y - vi0.y, e1z = pv0.z - vi0.z;
            float e2x = fst0.x - vi0.x, e2y = fst0.y - vi0.y, e2z = fst0.z - vi0.z;
            nx0 += e1y * e2z - e1z * e2y;
            ny0 += e1z * e2x - e1x * e2z;
            nz0 += e1x * e2y - e1y * e2x;
        }
        {
            float e1x = pv1.x - vi1.x, e1y = pv1.y - vi1.y, e1z = pv1.z - vi1.z;
            float e2x = fst1.x - vi1.x, e2y = fst1.y - vi1.y, e2z = fst1.z - vi1.z;
            nx1 += e1y * e2z - e1z * e2y;
            ny1 += e1z * e2x - e1x * e2z;
            nz1 += e1x * e2y - e1y * e2x;
        }

        const float* tb0 = tgt + (size_t)b0 * 9 * NVERTS + i;
        const float* tb1 = tgt + (size_t)(b0 + 1) * 9 * NVERTS + i;
        per_batch_loss(vi0.x, vi0.y, vi0.z, nx0, ny0, nz0, sx0, sy0, sz0, invd, tb0, sq, nor);
        per_batch_loss(vi1.x, vi1.y, vi1.z, nx1, ny1, nz1, sx1, sy1, sz1, invd, tb1, sq, nor);
    }

    // block reduction
    #pragma unroll
    for (int o = 16; o > 0; o >>= 1) {
        sq  += __shfl_down_sync(0xFFFFFFFFu, sq,  o);
        nor += __shfl_down_sync(0xFFFFFFFFu, nor, o);
    }
    __shared__ float s_sq[8], s_nor[8];
    int lane = threadIdx.x & 31, wid = threadIdx.x >> 5;
    if (lane == 0) { s_sq[wid] = sq; s_nor[wid] = nor; }
    __syncthreads();
    if (threadIdx.x == 0) {
        float a = 0.f, b = 0.f;
        #pragma unroll
        for (int w = 0; w < 8; w++) { a += s_sq[w]; b += s_nor[w]; }
        atomicAdd(&g_acc[0], (double)a);
        atomicAdd(&g_acc[1], (double)b);
    }
}

__global__ void k_final(float* __restrict__ out) {
    double l_sq  = g_acc[0] / ((double)BATCH * (double)NVERTS * 3.0);
    double l_nor = g_acc[1] / ((double)BATCH * (double)NVERTS);
    out[0] = (float)(l_sq + l_nor);
}

// ---------------- launch --------------------------------------------------
extern "C" void kernel_launch(void* const* d_in, const int* in_sizes, int n_in,
                              void* d_out, int out_size)
{
    const float* inputs = (const float*)d_in[0];
    const float* target = (const float*)d_in[1];
    const int*   faces  = (const int*)d_in[2];
    // d_in[3]=edge_src, d_in[4]=edge_dst : not needed (ring covers both)
    const float* degree = (const float*)d_in[5];
    float* out = (float*)d_out;

    int nbv = (NVERTS + 255) / 256;
    int nbf = (NFACES + 255) / 256;

    k_zero<<<nbv, 256>>>();
    k_build_v<<<dim3(nbv, BATCH / 2), 256>>>(inputs);
    k_build_inc<<<nbf, 256>>>(faces);
    k_build_ring<<<nbv, 256>>>(degree);
    k_main<<<dim3(nbv, BATCH / 2), 256>>>(target, degree);
    k_final<<<1, 1>>>(out);
}